// round 3
// baseline (speedup 1.0000x reference)
#include <cuda_runtime.h>

// Dice score: input (B=4, C=5, 128^3) fp32 logits, target (4, 128^3) int class ids.
// pred = argmax over C; per-batch per-class counts of pred / target / intersection
// (classes 1..4); dice = (2I+eps)/(P+T+eps); mean over 16 values -> out[0].
//
// Two launches:
//   k_count: per-block int64/int32 target detection, ballot-histogram counting,
//            global atomics into g_cnt (guaranteed zero at entry — see k_final).
//   k_final: computes the scalar, then re-zeroes g_cnt so the invariant
//            "g_cnt == 0 at kernel_launch entry" holds for every replay.

#define NB 4
#define NC 5
#define NPOS (1 << 21)                   // 128^3
#define TPB 256
#define POS_PER_THREAD 64
#define POS_PER_BLOCK (TPB * POS_PER_THREAD)   // 16384, divides NPOS
#define NBLOCKS ((NB * NPOS) / POS_PER_BLOCK)  // 512 -> single resident wave
#define NQUAD (POS_PER_THREAD / 4)             // 16

// flat: [b][kind*4 + (c-1)], kind 0=pred,1=tgt,2=inter. Zero at entry (see k_final).
__device__ int g_cnt[NB * 12];

__global__ void __launch_bounds__(TPB) k_count(const float* __restrict__ inp,
                                               const void* __restrict__ tgt) {
    __shared__ int s_cnt[12];
    __shared__ int s_is64;
    const int tid  = threadIdx.x;
    const int lane = tid & 31;
    if (tid < 12) s_cnt[tid] = 0;
    if (tid == 0) {
        // int32 buffer read as int64 -> value has a class id in the high word
        // whenever that word != 0; P(first 64 high words all zero) ~ (1/5)^64.
        const long long* t64 = (const long long*)tgt;
        int ok = 1;
        for (int i = 0; i < 64; i++) {
            long long v = t64[i];
            if (v < 0 || v > (NC - 1)) { ok = 0; break; }
        }
        s_is64 = ok;
    }
    __syncthreads();

    const long blockbase = (long)blockIdx.x * POS_PER_BLOCK;
    const int  b  = (int)(blockbase >> 21);
    const long n0 = (blockbase & (NPOS - 1)) + (long)tid * 4;
    const float* base = inp + (long)b * NC * NPOS + n0;
    const int is64 = s_is64;

    int pcnt[4] = {0, 0, 0, 0};
    int tcnt[4] = {0, 0, 0, 0};
    int icnt[4] = {0, 0, 0, 0};

    #pragma unroll 4
    for (int j = 0; j < NQUAD; j++) {
        // ---- targets: 4 positions ----
        const long gq = (blockbase >> 2) + (long)j * TPB + tid;  // quad index
        int tv[4];
        if (is64) {
            longlong4 t4 = ((const longlong4*)tgt)[gq];
            tv[0] = (int)t4.x; tv[1] = (int)t4.y; tv[2] = (int)t4.z; tv[3] = (int)t4.w;
        } else {
            int4 t4 = ((const int4*)tgt)[gq];
            tv[0] = t4.x; tv[1] = t4.y; tv[2] = t4.z; tv[3] = t4.w;
        }

        // ---- logits: 5 classes x float4 ----
        float va[NC][4];
        #pragma unroll
        for (int c = 0; c < NC; c++) {
            float4 v = *(const float4*)(base + (long)c * NPOS + (long)j * (TPB * 4));
            va[c][0] = v.x; va[c][1] = v.y; va[c][2] = v.z; va[c][3] = v.w;
        }

        // ---- per position: vmax + warp-ballot histogram ----
        #pragma unroll
        for (int k = 0; k < 4; k++) {
            const float f0 = va[0][k], f1 = va[1][k], f2 = va[2][k],
                        f3 = va[3][k], f4 = va[4][k];
            const float m = fmaxf(fmaxf(fmaxf(f0, f1), fmaxf(f2, f3)), f4);

            const unsigned pm1 = __ballot_sync(0xffffffffu, f1 == m);
            const unsigned pm2 = __ballot_sync(0xffffffffu, f2 == m);
            const unsigned pm3 = __ballot_sync(0xffffffffu, f3 == m);
            const unsigned pm4 = __ballot_sync(0xffffffffu, f4 == m);

            const int t = tv[k];
            const unsigned tm1 = __ballot_sync(0xffffffffu, t == 1);
            const unsigned tm2 = __ballot_sync(0xffffffffu, t == 2);
            const unsigned tm3 = __ballot_sync(0xffffffffu, t == 3);
            const unsigned tm4 = __ballot_sync(0xffffffffu, t == 4);

            pcnt[0] += __popc(pm1); pcnt[1] += __popc(pm2);
            pcnt[2] += __popc(pm3); pcnt[3] += __popc(pm4);
            tcnt[0] += __popc(tm1); tcnt[1] += __popc(tm2);
            tcnt[2] += __popc(tm3); tcnt[3] += __popc(tm4);
            icnt[0] += __popc(pm1 & tm1); icnt[1] += __popc(pm2 & tm2);
            icnt[2] += __popc(pm3 & tm3); icnt[3] += __popc(pm4 & tm4);
        }
    }

    // warp -> block: all lanes hold identical ballot sums, lane 0 contributes
    if (lane == 0) {
        #pragma unroll
        for (int c = 0; c < 4; c++) {
            atomicAdd(&s_cnt[0 * 4 + c], pcnt[c]);
            atomicAdd(&s_cnt[1 * 4 + c], tcnt[c]);
            atomicAdd(&s_cnt[2 * 4 + c], icnt[c]);
        }
    }
    __syncthreads();

    // block -> global (48 addresses total, ~128 REDs each, fully overlapped)
    if (tid < 12) atomicAdd(&g_cnt[b * 12 + tid], s_cnt[tid]);
}

__global__ void k_final(float* __restrict__ out) {
    __shared__ int s[NB * 12];
    const int tid = threadIdx.x;
    if (tid < NB * 12) {
        s[tid] = g_cnt[tid];
        g_cnt[tid] = 0;        // restore the zero-at-entry invariant for next launch
    }
    __syncthreads();
    if (tid == 0) {
        float acc = 0.0f;
        #pragma unroll
        for (int b = 0; b < NB; b++) {
            #pragma unroll
            for (int ci = 0; ci < 4; ci++) {
                const float I = (float)s[b * 12 + 8 + ci];
                const float U = (float)(s[b * 12 + ci] + s[b * 12 + 4 + ci]);
                acc += (2.0f * I + 1e-5f) / (U + 1e-5f);
            }
        }
        out[0] = acc * (1.0f / 16.0f);
    }
}

extern "C" void kernel_launch(void* const* d_in, const int* in_sizes, int n_in,
                              void* d_out, int out_size) {
    const float* inp = (const float*)d_in[0];
    const void*  tgt = d_in[1];
    float* out = (float*)d_out;
    (void)in_sizes; (void)n_in; (void)out_size;

    k_count<<<NBLOCKS, TPB>>>(inp, tgt);
    k_final<<<1, 64>>>(out);
}